// round 1
// baseline (speedup 1.0000x reference)
#include <cuda_runtime.h>
#include <math.h>

#define NN 4096
#define MM 8192
#define DD 128
#define INV_T 10.0f
#define CBIAS 10.0f
#define KC 32
#define CSPLIT 16
#define CT_PER 4   // 64 column tiles / 16 splits

__device__ __align__(16) float g_zn[MM * DD];
__device__ float g_rowsum[MM];
__device__ float g_partner[MM];

// ---------------------------------------------------------------------------
// Kernel 1: row L2-normalize z = concat(z1, z2); also zero g_rowsum (every
// graph replay re-zeros, keeping kernel_launch deterministic).
// ---------------------------------------------------------------------------
__global__ void normalize_kernel(const float* __restrict__ z1,
                                 const float* __restrict__ z2) {
    int row = blockIdx.x;
    int t = threadIdx.x;
    const float* src = (row < NN) ? (z1 + (size_t)row * DD)
                                  : (z2 + (size_t)(row - NN) * DD);
    float v = src[t];
    float ss = v * v;
    #pragma unroll
    for (int o = 16; o; o >>= 1) ss += __shfl_xor_sync(0xffffffffu, ss, o);
    __shared__ float sred[4];
    if ((t & 31) == 0) sred[t >> 5] = ss;
    __syncthreads();
    float tot = sred[0] + sred[1] + sred[2] + sred[3];
    float inv = 1.0f / fmaxf(sqrtf(tot), 1e-8f);
    g_zn[(size_t)row * DD + t] = v * inv;
    if (t == 0) g_rowsum[row] = 0.0f;
}

// ---------------------------------------------------------------------------
// Kernel 2: streaming sim tiles + fused exp accumulation.
// Block = (split sp, row-tile rt). Handles 128 rows x 4 column tiles of 128.
// 8x8 register tile per thread, k-major smem for vectorized LDS.128.
// ---------------------------------------------------------------------------
__global__ __launch_bounds__(256, 2) void sim_kernel() {
    __shared__ float As[KC][132];
    __shared__ float Bs[KC][132];

    int tid = threadIdx.x;
    int tx = tid & 15;
    int ty = tid >> 4;
    int rt = blockIdx.y;   // 0..63
    int sp = blockIdx.x;   // 0..15
    int row0 = rt * 128;

    float rowSum[8];
    #pragma unroll
    for (int r = 0; r < 8; r++) rowSum[r] = 0.0f;

    for (int ctile = 0; ctile < CT_PER; ctile++) {
        int col0 = (sp * CT_PER + ctile) * 128;

        float acc[8][8];
        #pragma unroll
        for (int r = 0; r < 8; r++)
            #pragma unroll
            for (int c = 0; c < 8; c++) acc[r][c] = 0.0f;

        for (int k0 = 0; k0 < DD; k0 += KC) {
            __syncthreads();
            // cooperative load: 128 rows x 32 k into k-major smem
            #pragma unroll
            for (int p = 0; p < 4; p++) {
                int s = tid + 256 * p;
                int lrow = s >> 3;
                int q = s & 7;
                float4 va = *(const float4*)(g_zn + (size_t)(row0 + lrow) * DD + k0 + q * 4);
                As[q * 4 + 0][lrow] = va.x;
                As[q * 4 + 1][lrow] = va.y;
                As[q * 4 + 2][lrow] = va.z;
                As[q * 4 + 3][lrow] = va.w;
                float4 vb = *(const float4*)(g_zn + (size_t)(col0 + lrow) * DD + k0 + q * 4);
                Bs[q * 4 + 0][lrow] = vb.x;
                Bs[q * 4 + 1][lrow] = vb.y;
                Bs[q * 4 + 2][lrow] = vb.z;
                Bs[q * 4 + 3][lrow] = vb.w;
            }
            __syncthreads();

            #pragma unroll 8
            for (int kk = 0; kk < KC; kk++) {
                float4 a0 = *(const float4*)&As[kk][ty * 8];
                float4 a1 = *(const float4*)&As[kk][ty * 8 + 4];
                float4 b0 = *(const float4*)&Bs[kk][tx * 8];
                float4 b1 = *(const float4*)&Bs[kk][tx * 8 + 4];
                float a[8] = {a0.x, a0.y, a0.z, a0.w, a1.x, a1.y, a1.z, a1.w};
                float b[8] = {b0.x, b0.y, b0.z, b0.w, b1.x, b1.y, b1.z, b1.w};
                #pragma unroll
                for (int r = 0; r < 8; r++)
                    #pragma unroll
                    for (int c = 0; c < 8; c++)
                        acc[r][c] = fmaf(a[r], b[c], acc[r][c]);
            }
        }

        // fused epilogue: scale, diag exclusion, partner capture, exp-accumulate
        #pragma unroll
        for (int r = 0; r < 8; r++) {
            int gi = row0 + ty * 8 + r;
            int part = (gi < NN) ? gi + NN : gi - NN;
            #pragma unroll
            for (int c = 0; c < 8; c++) {
                int gj = col0 + tx * 8 + c;
                float s = acc[r][c] * INV_T;
                if (gj == part) g_partner[gi] = s;   // exactly one writer per row
                float e = (gj == gi) ? 0.0f : __expf(s - CBIAS);
                rowSum[r] += e;
            }
        }
    }

    // reduce rowSum across the 16 tx-threads sharing the same 8 rows.
    // lane = (ty&1)*16 + tx  -> xor offsets 1,2,4,8 stay within 16-lane half.
    #pragma unroll
    for (int r = 0; r < 8; r++) {
        float v = rowSum[r];
        #pragma unroll
        for (int o = 8; o; o >>= 1) v += __shfl_xor_sync(0xffffffffu, v, o);
        rowSum[r] = v;
    }
    if (tx == 0) {
        #pragma unroll
        for (int r = 0; r < 8; r++)
            atomicAdd(&g_rowsum[row0 + ty * 8 + r], rowSum[r]);
    }
}

// ---------------------------------------------------------------------------
// Kernel 3: finalize. loss = sum_i (lse_i - pos_i) / (M*M)
// ---------------------------------------------------------------------------
__global__ void finalize_kernel(float* __restrict__ out) {
    int tid = threadIdx.x;
    float local = 0.0f;
    for (int i = tid; i < MM; i += 1024) {
        int part = (i < NN) ? i + NN : i - NN;
        float pos = g_partner[i] + g_partner[part];
        float lse = logf(g_rowsum[i] + __expf(pos - CBIAS)) + CBIAS;
        local += lse - pos;
    }
    #pragma unroll
    for (int o = 16; o; o >>= 1) local += __shfl_xor_sync(0xffffffffu, local, o);
    __shared__ float sr[32];
    if ((tid & 31) == 0) sr[tid >> 5] = local;
    __syncthreads();
    if (tid < 32) {
        float v = sr[tid];
        #pragma unroll
        for (int o = 16; o; o >>= 1) v += __shfl_xor_sync(0xffffffffu, v, o);
        if (tid == 0) out[0] = v / ((float)MM * (float)MM);
    }
}

extern "C" void kernel_launch(void* const* d_in, const int* in_sizes, int n_in,
                              void* d_out, int out_size) {
    const float* z1 = (const float*)d_in[0];
    const float* z2 = (const float*)d_in[1];
    float* out = (float*)d_out;

    normalize_kernel<<<MM, 128>>>(z1, z2);
    dim3 grid(CSPLIT, MM / 128);
    sim_kernel<<<grid, 256>>>();
    finalize_kernel<<<1, 1024>>>(out);
}

// round 5
// speedup vs baseline: 6.0199x; 6.0199x over previous
#include <cuda_runtime.h>
#include <cuda_bf16.h>
#include <math.h>
#include <cstdint>

#define NN 4096
#define MM 8192
#define DD 128
#define CBIAS 10.0f
#define SQRT10 3.162277660168379f

// ---------------- device globals (no allocs allowed) ----------------------
__device__ __align__(16) __nv_bfloat16 g_zbf[MM * DD];  // normalized * sqrt(10), row-major
__device__ float g_rowsum[MM];
__device__ float g_partner[NN];   // sim[i, i+N] (upper partner), i < N

// ---------------- helpers --------------------------------------------------
__device__ __forceinline__ uint32_t smem_to_u32(const void* p) {
    uint32_t a;
    asm("{ .reg .u64 t; cvta.to.shared.u64 t, %1; cvt.u32.u64 %0, t; }"
        : "=r"(a) : "l"(p));
    return a;
}

#define LDSM_X4(r0, r1, r2, r3, addr)                                          \
    asm volatile("ldmatrix.sync.aligned.m8n8.x4.shared.b16 {%0,%1,%2,%3}, [%4];" \
        : "=r"(r0), "=r"(r1), "=r"(r2), "=r"(r3) : "r"(addr))

#define LDSM_X2(r0, r1, addr)                                                  \
    asm volatile("ldmatrix.sync.aligned.m8n8.x2.shared.b16 {%0,%1}, [%2];"     \
        : "=r"(r0), "=r"(r1) : "r"(addr))

#define MMA16816(d, a0, a1, a2, a3, b0, b1)                                    \
    asm volatile("mma.sync.aligned.m16n8k16.row.col.f32.bf16.bf16.f32 "        \
        "{%0,%1,%2,%3}, {%4,%5,%6,%7}, {%8,%9}, {%0,%1,%2,%3};"                \
        : "+f"((d)[0]), "+f"((d)[1]), "+f"((d)[2]), "+f"((d)[3])               \
        : "r"(a0), "r"(a1), "r"(a2), "r"(a3), "r"(b0), "r"(b1))

// ---------------------------------------------------------------------------
// Kernel 1: normalize rows, scale by sqrt(10), convert to bf16 row-major.
// Also zeroes g_rowsum for this replay (graph-replay deterministic).
// ---------------------------------------------------------------------------
__global__ void normalize_kernel(const float* __restrict__ z1,
                                 const float* __restrict__ z2) {
    int row = blockIdx.x;
    int t = threadIdx.x;
    const float* src = (row < NN) ? (z1 + (size_t)row * DD)
                                  : (z2 + (size_t)(row - NN) * DD);
    float v = src[t];
    float ss = v * v;
    #pragma unroll
    for (int o = 16; o; o >>= 1) ss += __shfl_xor_sync(0xffffffffu, ss, o);
    __shared__ float sred[4];
    if ((t & 31) == 0) sred[t >> 5] = ss;
    __syncthreads();
    float tot = sred[0] + sred[1] + sred[2] + sred[3];
    float inv = SQRT10 / fmaxf(sqrtf(tot), 1e-8f);
    g_zbf[(size_t)row * DD + t] = __float2bfloat16(v * inv);
    if (t == 0) g_rowsum[row] = 0.0f;
}

// ---------------------------------------------------------------------------
// Kernel 2: symmetric bf16 HMMA sim tiles (128x128), fused exp epilogue.
// Only upper-triangular tiles (ct >= rt); each exp credited to rowsum[gi]
// and rowsum[gj] (column sum == transposed row sum by symmetry).
// SMEM tiles: 128 rows x 256B, XOR-swizzled 16B chunks for conflict-free
// ldmatrix:  byte(r, kb) = r*256 + ((kb*16) ^ ((r&7)*16)),  kb = 16B chunk.
// ---------------------------------------------------------------------------
__global__ void __launch_bounds__(256, 2) sim_kernel() {
    int rt = blockIdx.x, ct = blockIdx.y;
    if (ct < rt) return;
    bool diag = (ct == rt);

    extern __shared__ __align__(128) unsigned char smem[];
    uint32_t sb = smem_to_u32(smem);
    uint32_t smA = sb, smB = sb + 32768;

    int tid = threadIdx.x;
    int lane = tid & 31, wid = tid >> 5;
    int wr = wid >> 2, wc = wid & 3;       // 2x4 warps; warp tile 64r x 32c
    int row0 = rt * 128, col0 = ct * 128;

    // ---- load tiles global -> swizzled smem (16B chunks, coalesced src) ----
    {
        const uint4* srcA = (const uint4*)(g_zbf + (size_t)row0 * DD);
        const uint4* srcB = (const uint4*)(g_zbf + (size_t)col0 * DD);
        #pragma unroll
        for (int i = 0; i < 8; i++) {
            int s = tid + 256 * i;          // chunk id 0..2047
            int r = s >> 4, kb = s & 15;
            uint32_t off = (uint32_t)(r * 256) + (uint32_t)((kb * 16) ^ ((r & 7) * 16));
            *(uint4*)(smem + off) = srcA[s];
            *(uint4*)(smem + 32768 + off) = srcB[s];
        }
    }
    __syncthreads();

    // ---- fragment addresses ----
    int rA = wr * 64 + (lane & 7) + ((lane >> 3) & 1) * 8;   // + mi*16
    uint32_t xorA = (uint32_t)((rA & 7) << 4);
    int kbA_half = (lane >> 4);                               // 0/1 -> +8 in k
    uint32_t baseA[4];
    #pragma unroll
    for (int mi = 0; mi < 4; mi++) baseA[mi] = smA + (uint32_t)((rA + mi * 16) * 256);

    int rB = wc * 32 + (lane & 7);                            // + ni*8
    uint32_t xorB = (uint32_t)((rB & 7) << 4);
    int kbB_half = (lane >> 3) & 1;
    uint32_t baseB[4];
    #pragma unroll
    for (int ni = 0; ni < 4; ni++) baseB[ni] = smB + (uint32_t)((rB + ni * 8) * 256);

    float acc[4][4][4];
    #pragma unroll
    for (int mi = 0; mi < 4; mi++)
        #pragma unroll
        for (int ni = 0; ni < 4; ni++)
            #pragma unroll
            for (int e = 0; e < 4; e++) acc[mi][ni][e] = 0.0f;

    // ---- mainloop: 8 k-steps of m16n8k16 ----
    #pragma unroll
    for (int ks = 0; ks < 8; ks++) {
        uint32_t a[4][4], b[4][2];
        uint32_t kbA = (uint32_t)((ks * 2 + kbA_half) * 16);
        #pragma unroll
        for (int mi = 0; mi < 4; mi++)
            LDSM_X4(a[mi][0], a[mi][1], a[mi][2], a[mi][3], baseA[mi] + (kbA ^ xorA));
        uint32_t kbB = (uint32_t)((ks * 2 + kbB_half) * 16);
        #pragma unroll
        for (int ni = 0; ni < 4; ni++)
            LDSM_X2(b[ni][0], b[ni][1], baseB[ni] + (kbB ^ xorB));
        #pragma unroll
        for (int mi = 0; mi < 4; mi++)
            #pragma unroll
            for (int ni = 0; ni < 4; ni++)
                MMA16816(acc[mi][ni], a[mi][0], a[mi][1], a[mi][2], a[mi][3],
                         b[ni][0], b[ni][1]);
    }

    // ---- fused epilogue: exp + symmetric row/col accumulation ----
    // D fragment: e0:(g,2t) e1:(g,2t+1) e2:(g+8,2t) e3:(g+8,2t+1), g=lane>>2, t=lane&3
    int g = lane >> 2, th = lane & 3;
    float rsum[4][2];   // [mi][h]
    float csum[4][2];   // [ni][p]
    #pragma unroll
    for (int i = 0; i < 4; i++) { rsum[i][0] = rsum[i][1] = 0.0f;
                                  csum[i][0] = csum[i][1] = 0.0f; }

    #pragma unroll
    for (int mi = 0; mi < 4; mi++) {
        #pragma unroll
        for (int ni = 0; ni < 4; ni++) {
            #pragma unroll
            for (int e = 0; e < 4; e++) {
                int h = e >> 1, p = e & 1;
                int gi = row0 + wr * 64 + mi * 16 + g + h * 8;
                int gj = col0 + wc * 32 + ni * 8 + th * 2 + p;
                float v = acc[mi][ni][e];
                if (gj == gi + NN) g_partner[gi] = v;      // unique upper partner
                bool take = diag ? (gj > gi) : true;
                if (take) {
                    float ex = __expf(v - CBIAS);
                    rsum[mi][h] += ex;
                    csum[ni][p] += ex;
                }
            }
        }
    }

    // row sums: reduce across th (lanes xor 1,2); th==0 lanes hold 32-col sums
    #pragma unroll
    for (int mi = 0; mi < 4; mi++)
        #pragma unroll
        for (int h = 0; h < 2; h++) {
            float v = rsum[mi][h];
            v += __shfl_xor_sync(0xffffffffu, v, 1);
            v += __shfl_xor_sync(0xffffffffu, v, 2);
            if (th == 0)
                atomicAdd(&g_rowsum[row0 + wr * 64 + mi * 16 + g + h * 8], v);
        }

    // col sums: reduce across g (lanes xor 4,8,16); lanes 0-3 hold 64-row sums
    #pragma unroll
    for (int ni = 0; ni < 4; ni++)
        #pragma unroll
        for (int p = 0; p < 2; p++) {
            float v = csum[ni][p];
            v += __shfl_xor_sync(0xffffffffu, v, 4);
            v += __shfl_xor_sync(0xffffffffu, v, 8);
            v += __shfl_xor_sync(0xffffffffu, v, 16);
            if (lane < 4)
                atomicAdd(&g_rowsum[col0 + wc * 32 + ni * 8 + lane * 2 + p], v);
        }
}

// ---------------------------------------------------------------------------
// Kernel 3: finalize. pos_i = 2*sim[i,i+N]; loss = sum_i (lse_i - pos_i)/(M*M)
// ---------------------------------------------------------------------------
__global__ void finalize_kernel(float* __restrict__ out) {
    int tid = threadIdx.x;
    float local = 0.0f;
    for (int i = tid; i < MM; i += 1024) {
        float pv = g_partner[(i < NN) ? i : i - NN];
        float pos = 2.0f * pv;
        float lse = logf(g_rowsum[i] + __expf(pos - CBIAS)) + CBIAS;
        local += lse - pos;
    }
    #pragma unroll
    for (int o = 16; o; o >>= 1) local += __shfl_xor_sync(0xffffffffu, local, o);
    __shared__ float sr[32];
    if ((tid & 31) == 0) sr[tid >> 5] = local;
    __syncthreads();
    if (tid < 32) {
        float v = sr[tid];
        #pragma unroll
        for (int o = 16; o; o >>= 1) v += __shfl_xor_sync(0xffffffffu, v, o);
        if (tid == 0) out[0] = v / ((float)MM * (float)MM);
    }
}

extern "C" void kernel_launch(void* const* d_in, const int* in_sizes, int n_in,
                              void* d_out, int out_size) {
    const float* z1 = (const float*)d_in[0];
    const float* z2 = (const float*)d_in[1];
    float* out = (float*)d_out;

    cudaFuncSetAttribute(sim_kernel, cudaFuncAttributeMaxDynamicSharedMemorySize, 65536);

    normalize_kernel<<<MM, 128>>>(z1, z2);
    dim3 grid(64, 64);
    sim_kernel<<<grid, 256, 65536>>>();
    finalize_kernel<<<1, 1024>>>(out);
}

// round 6
// speedup vs baseline: 6.2535x; 1.0388x over previous
#include <cuda_runtime.h>
#include <cuda_bf16.h>
#include <math.h>
#include <cstdint>

#define NN 4096
#define MM 8192
#define DD 128
#define CBIAS 10.0f
#define SQRT10 3.162277660168379f
#define NTILE 64
#define NTRI (NTILE * (NTILE + 1) / 2)   // 2080

// ---------------- device globals (no allocs allowed) ----------------------
__device__ __align__(16) __nv_bfloat16 g_zbf[MM * DD];  // normalized * sqrt(10)
__device__ float g_rowsum[MM];
__device__ float g_partner[NN];   // sim[i, i+N], i < N

// ---------------- helpers --------------------------------------------------
__device__ __forceinline__ uint32_t smem_to_u32(const void* p) {
    uint32_t a;
    asm("{ .reg .u64 t; cvta.to.shared.u64 t, %1; cvt.u32.u64 %0, t; }"
        : "=r"(a) : "l"(p));
    return a;
}

#define LDSM_X4(r0, r1, r2, r3, addr)                                          \
    asm volatile("ldmatrix.sync.aligned.m8n8.x4.shared.b16 {%0,%1,%2,%3}, [%4];" \
        : "=r"(r0), "=r"(r1), "=r"(r2), "=r"(r3) : "r"(addr))

#define LDSM_X2(r0, r1, addr)                                                  \
    asm volatile("ldmatrix.sync.aligned.m8n8.x2.shared.b16 {%0,%1}, [%2];"     \
        : "=r"(r0), "=r"(r1) : "r"(addr))

#define MMA16816(d, a0, a1, a2, a3, b0, b1)                                    \
    asm volatile("mma.sync.aligned.m16n8k16.row.col.f32.bf16.bf16.f32 "        \
        "{%0,%1,%2,%3}, {%4,%5,%6,%7}, {%8,%9}, {%0,%1,%2,%3};"                \
        : "+f"((d)[0]), "+f"((d)[1]), "+f"((d)[2]), "+f"((d)[3])               \
        : "r"(a0), "r"(a1), "r"(a2), "r"(a3), "r"(b0), "r"(b1))

#define CP_ASYNC16(sm, gp)                                                     \
    asm volatile("cp.async.cg.shared.global [%0], [%1], 16;"                   \
        :: "r"(sm), "l"(gp) : "memory")
#define CP_COMMIT  asm volatile("cp.async.commit_group;" ::: "memory")
#define CP_WAIT0   asm volatile("cp.async.wait_group 0;" ::: "memory")

// ---------------------------------------------------------------------------
// Kernel 1: warp-per-row normalize. lane holds exactly 4 floats (float4).
// Writes bf16 * sqrt(10); zeroes g_rowsum for this replay.
// ---------------------------------------------------------------------------
__global__ void __launch_bounds__(1024) normalize_kernel(
        const float* __restrict__ z1, const float* __restrict__ z2) {
    int w = (blockIdx.x * 1024 + threadIdx.x) >> 5;   // row 0..8191
    int lane = threadIdx.x & 31;
    const float* src = (w < NN) ? (z1 + (size_t)w * DD)
                                : (z2 + (size_t)(w - NN) * DD);
    float4 v = ((const float4*)src)[lane];
    float ss = v.x * v.x + v.y * v.y + v.z * v.z + v.w * v.w;
    #pragma unroll
    for (int o = 16; o; o >>= 1) ss += __shfl_xor_sync(0xffffffffu, ss, o);
    float inv = SQRT10 / fmaxf(sqrtf(ss), 1e-8f);
    __nv_bfloat162 p0 = {__float2bfloat16(v.x * inv), __float2bfloat16(v.y * inv)};
    __nv_bfloat162 p1 = {__float2bfloat16(v.z * inv), __float2bfloat16(v.w * inv)};
    uint2 out;
    out.x = *(uint32_t*)&p0;
    out.y = *(uint32_t*)&p1;
    ((uint2*)(g_zbf + (size_t)w * DD))[lane] = out;
    if (lane == 0) g_rowsum[w] = 0.0f;
}

// ---------------------------------------------------------------------------
// Kernel 2: symmetric bf16 HMMA sim tiles (128x128), fused exp epilogue.
// Exactly NTRI CTAs, linear index unranked to upper-triangular (rt, ct).
// ---------------------------------------------------------------------------
__global__ void __launch_bounds__(256, 2) sim_kernel() {
    // unrank blockIdx.x -> (rt, ct), rt <= ct
    int rt = 0, rem = blockIdx.x;
    #pragma unroll 1
    while (rem >= NTILE - rt) { rem -= NTILE - rt; rt++; }
    int ct = rt + rem;
    bool diag = (ct == rt);
    bool pblock = (ct == rt + NTILE / 2);   // only these tiles hold partners

    extern __shared__ __align__(128) unsigned char smem[];
    uint32_t sb = smem_to_u32(smem);
    uint32_t smA = sb, smB = sb + 32768;

    int tid = threadIdx.x;
    int lane = tid & 31, wid = tid >> 5;
    int wr = wid >> 2, wc = wid & 3;        // 2x4 warps; warp tile 64r x 32c
    int row0 = rt * 128, col0 = ct * 128;

    // ---- async tile loads global -> swizzled smem ----
    {
        const uint4* srcA = (const uint4*)(g_zbf + (size_t)row0 * DD);
        const uint4* srcB = (const uint4*)(g_zbf + (size_t)col0 * DD);
        #pragma unroll
        for (int i = 0; i < 8; i++) {
            int s = tid + 256 * i;          // 16B chunk id 0..2047
            int r = s >> 4, kb = s & 15;
            uint32_t off = (uint32_t)(r * 256) + (uint32_t)((kb * 16) ^ ((r & 7) * 16));
            CP_ASYNC16(smA + off, srcA + s);
            CP_ASYNC16(smB + off, srcB + s);
        }
        CP_COMMIT;
    }
    CP_WAIT0;
    __syncthreads();

    // ---- fragment addresses ----
    int rA = wr * 64 + (lane & 7) + ((lane >> 3) & 1) * 8;
    uint32_t xorA = (uint32_t)((rA & 7) << 4);
    int kbA_half = (lane >> 4);
    uint32_t baseA[4];
    #pragma unroll
    for (int mi = 0; mi < 4; mi++) baseA[mi] = smA + (uint32_t)((rA + mi * 16) * 256);

    int rB = wc * 32 + (lane & 7);
    uint32_t xorB = (uint32_t)((rB & 7) << 4);
    int kbB_half = (lane >> 3) & 1;
    uint32_t baseB[4];
    #pragma unroll
    for (int ni = 0; ni < 4; ni++) baseB[ni] = smB + (uint32_t)((rB + ni * 8) * 256);

    float acc[4][4][4];
    #pragma unroll
    for (int mi = 0; mi < 4; mi++)
        #pragma unroll
        for (int ni = 0; ni < 4; ni++)
            #pragma unroll
            for (int e = 0; e < 4; e++) acc[mi][ni][e] = 0.0f;

    // ---- mainloop: 8 k-steps of m16n8k16 ----
    #pragma unroll
    for (int ks = 0; ks < 8; ks++) {
        uint32_t a[4][4], b[4][2];
        uint32_t kbA = (uint32_t)((ks * 2 + kbA_half) * 16);
        #pragma unroll
        for (int mi = 0; mi < 4; mi++)
            LDSM_X4(a[mi][0], a[mi][1], a[mi][2], a[mi][3], baseA[mi] + (kbA ^ xorA));
        uint32_t kbB = (uint32_t)((ks * 2 + kbB_half) * 16);
        #pragma unroll
        for (int ni = 0; ni < 4; ni++)
            LDSM_X2(b[ni][0], b[ni][1], baseB[ni] + (kbB ^ xorB));
        #pragma unroll
        for (int mi = 0; mi < 4; mi++)
            #pragma unroll
            for (int ni = 0; ni < 4; ni++)
                MMA16816(acc[mi][ni], a[mi][0], a[mi][1], a[mi][2], a[mi][3],
                         b[ni][0], b[ni][1]);
    }

    // ---- fused epilogue: exp + symmetric row/col accumulation ----
    int g = lane >> 2, th = lane & 3;
    float rsum[4][2], csum[4][2];
    #pragma unroll
    for (int i = 0; i < 4; i++) { rsum[i][0] = rsum[i][1] = 0.0f;
                                  csum[i][0] = csum[i][1] = 0.0f; }

    #pragma unroll
    for (int mi = 0; mi < 4; mi++) {
        int gi_b = row0 + wr * 64 + mi * 16 + g;
        #pragma unroll
        for (int ni = 0; ni < 4; ni++) {
            int gj_b = col0 + wc * 32 + ni * 8 + th * 2;
            #pragma unroll
            for (int e = 0; e < 4; e++) {
                int h = e >> 1, p = e & 1;
                int gi = gi_b + h * 8;
                int gj = gj_b + p;
                float v = acc[mi][ni][e];
                if (pblock && gj == gi + NN) g_partner[gi] = v;
                bool take = diag ? (gj > gi) : true;
                if (take) {
                    float ex = __expf(v - CBIAS);
                    rsum[mi][h] += ex;
                    csum[ni][p] += ex;
                }
            }
        }
    }

    #pragma unroll
    for (int mi = 0; mi < 4; mi++)
        #pragma unroll
        for (int h = 0; h < 2; h++) {
            float v = rsum[mi][h];
            v += __shfl_xor_sync(0xffffffffu, v, 1);
            v += __shfl_xor_sync(0xffffffffu, v, 2);
            if (th == 0)
                atomicAdd(&g_rowsum[row0 + wr * 64 + mi * 16 + g + h * 8], v);
        }

    #pragma unroll
    for (int ni = 0; ni < 4; ni++)
        #pragma unroll
        for (int p = 0; p < 2; p++) {
            float v = csum[ni][p];
            v += __shfl_xor_sync(0xffffffffu, v, 4);
            v += __shfl_xor_sync(0xffffffffu, v, 8);
            v += __shfl_xor_sync(0xffffffffu, v, 16);
            if (lane < 4)
                atomicAdd(&g_rowsum[col0 + wc * 32 + ni * 8 + lane * 2 + p], v);
        }
}

// ---------------------------------------------------------------------------
// Kernel 3: finalize. pos_i = 2*sim[i,i+N]; loss = sum_i (lse_i - pos_i)/(M*M)
// ---------------------------------------------------------------------------
__global__ void finalize_kernel(float* __restrict__ out) {
    int tid = threadIdx.x;
    float local = 0.0f;
    for (int i = tid; i < MM; i += 1024) {
        float pv = g_partner[(i < NN) ? i : i - NN];
        float pos = 2.0f * pv;
        float lse = logf(g_rowsum[i] + __expf(pos - CBIAS)) + CBIAS;
        local += lse - pos;
    }
    #pragma unroll
    for (int o = 16; o; o >>= 1) local += __shfl_xor_sync(0xffffffffu, local, o);
    __shared__ float sr[32];
    if ((tid & 31) == 0) sr[tid >> 5] = local;
    __syncthreads();
    if (tid < 32) {
        float v = sr[tid];
        #pragma unroll
        for (int o = 16; o; o >>= 1) v += __shfl_xor_sync(0xffffffffu, v, o);
        if (tid == 0) out[0] = v / ((float)MM * (float)MM);
    }
}

extern "C" void kernel_launch(void* const* d_in, const int* in_sizes, int n_in,
                              void* d_out, int out_size) {
    const float* z1 = (const float*)d_in[0];
    const float* z2 = (const float*)d_in[1];
    float* out = (float*)d_out;

    cudaFuncSetAttribute(sim_kernel, cudaFuncAttributeMaxDynamicSharedMemorySize, 65536);

    normalize_kernel<<<MM / 32, 1024>>>(z1, z2);
    sim_kernel<<<NTRI, 256, 65536>>>();
    finalize_kernel<<<1, 1024>>>(out);
}

// round 8
// speedup vs baseline: 9.5659x; 1.5297x over previous
#include <cuda_runtime.h>
#include <cuda_bf16.h>
#include <math.h>
#include <cstdint>

#define NN 4096
#define MM 8192
#define DD 128
#define NTILE 64
#define NTRI (NTILE * (NTILE + 1) / 2)   // 2080

// operands pre-scaled by sqrt(10 * log2(e)) so acc = log2(e) * sim / T
#define SCALE_IN 3.798282100420615f
#define CB2 14.426950408889634f          // 10 * log2(e)
#define LN2 0.6931471805599453f

// ---------------- device globals (no allocs allowed) ----------------------
__device__ __align__(16) __nv_bfloat16 g_zbf[MM * DD];
__device__ float g_rowsum[MM];
__device__ float g_partner[NN];   // log2e * sim[i, i+N] / T

// ---------------- helpers --------------------------------------------------
__device__ __forceinline__ uint32_t smem_to_u32(const void* p) {
    uint32_t a;
    asm("{ .reg .u64 t; cvta.to.shared.u64 t, %1; cvt.u32.u64 %0, t; }"
        : "=r"(a) : "l"(p));
    return a;
}

#define LDSM_X4(r0, r1, r2, r3, addr)                                          \
    asm volatile("ldmatrix.sync.aligned.m8n8.x4.shared.b16 {%0,%1,%2,%3}, [%4];" \
        : "=r"(r0), "=r"(r1), "=r"(r2), "=r"(r3) : "r"(addr))

#define LDSM_X2(r0, r1, addr)                                                  \
    asm volatile("ldmatrix.sync.aligned.m8n8.x2.shared.b16 {%0,%1}, [%2];"     \
        : "=r"(r0), "=r"(r1) : "r"(addr))

#define MMA16816(d, a0, a1, a2, a3, b0, b1)                                    \
    asm volatile("mma.sync.aligned.m16n8k16.row.col.f32.bf16.bf16.f32 "        \
        "{%0,%1,%2,%3}, {%4,%5,%6,%7}, {%8,%9}, {%0,%1,%2,%3};"                \
        : "+f"((d)[0]), "+f"((d)[1]), "+f"((d)[2]), "+f"((d)[3])               \
        : "r"(a0), "r"(a1), "r"(a2), "r"(a3), "r"(b0), "r"(b1))

#define CP_ASYNC16(sm, gp)                                                     \
    asm volatile("cp.async.cg.shared.global [%0], [%1], 16;"                   \
        :: "r"(sm), "l"(gp) : "memory")
#define CP_COMMIT  asm volatile("cp.async.commit_group;" ::: "memory")
#define CP_WAIT(n) asm volatile("cp.async.wait_group %0;" :: "n"(n) : "memory")

// ---------------------------------------------------------------------------
// Kernel 1: warp handles paired rows r (from z1) and r+NN (from z2).
// Two independent reduce chains per warp for ILP. Zeroes g_rowsum.
// ---------------------------------------------------------------------------
__global__ void __launch_bounds__(1024) normalize_kernel(
        const float* __restrict__ z1, const float* __restrict__ z2) {
    int r = (blockIdx.x * 1024 + threadIdx.x) >> 5;   // 0..NN-1
    int lane = threadIdx.x & 31;
    float4 a = ((const float4*)(z1 + (size_t)r * DD))[lane];
    float4 b = ((const float4*)(z2 + (size_t)r * DD))[lane];
    float sa = a.x * a.x + a.y * a.y + a.z * a.z + a.w * a.w;
    float sb = b.x * b.x + b.y * b.y + b.z * b.z + b.w * b.w;
    #pragma unroll
    for (int o = 16; o; o >>= 1) {
        sa += __shfl_xor_sync(0xffffffffu, sa, o);
        sb += __shfl_xor_sync(0xffffffffu, sb, o);
    }
    float ia = SCALE_IN * rsqrtf(sa);
    float ib = SCALE_IN * rsqrtf(sb);
    __nv_bfloat162 a0 = {__float2bfloat16(a.x * ia), __float2bfloat16(a.y * ia)};
    __nv_bfloat162 a1 = {__float2bfloat16(a.z * ia), __float2bfloat16(a.w * ia)};
    __nv_bfloat162 b0 = {__float2bfloat16(b.x * ib), __float2bfloat16(b.y * ib)};
    __nv_bfloat162 b1 = {__float2bfloat16(b.z * ib), __float2bfloat16(b.w * ib)};
    uint2 oa, ob;
    oa.x = *(uint32_t*)&a0; oa.y = *(uint32_t*)&a1;
    ob.x = *(uint32_t*)&b0; ob.y = *(uint32_t*)&b1;
    ((uint2*)(g_zbf + (size_t)r * DD))[lane] = oa;
    ((uint2*)(g_zbf + (size_t)(r + NN) * DD))[lane] = ob;
    if (lane == 0) { g_rowsum[r] = 0.0f; g_rowsum[r + NN] = 0.0f; }
}

// ---------------------------------------------------------------------------
// Kernel 2: symmetric bf16 HMMA sim tiles (128x128), split-K pipelined
// cp.async, exp2 epilogue, smem-staged reduction.
// ---------------------------------------------------------------------------
__global__ void __launch_bounds__(256, 2) sim_kernel() {
    int rt = 0, rem = blockIdx.x;
    #pragma unroll 1
    while (rem >= NTILE - rt) { rem -= NTILE - rt; rt++; }
    int ct = rt + rem;
    bool diag = (ct == rt);
    bool pblock = (ct == rt + NTILE / 2);

    extern __shared__ __align__(128) unsigned char smem[];
    uint32_t sb = smem_to_u32(smem);
    uint32_t smA = sb, smB = sb + 32768;

    int tid = threadIdx.x;
    int lane = tid & 31, wid = tid >> 5;
    int wr = wid >> 2, wc = wid & 3;        // 2x4 warps; warp tile 64r x 32c
    int row0 = rt * 128, col0 = ct * 128;

    // ---- split-K async tile loads: half h = k-chunks [8h, 8h+8) ----
    {
        const uint4* srcA = (const uint4*)(g_zbf + (size_t)row0 * DD);
        const uint4* srcB = (const uint4*)(g_zbf + (size_t)col0 * DD);
        #pragma unroll
        for (int h = 0; h < 2; h++) {
            #pragma unroll
            for (int j = 0; j < 4; j++) {
                int s2 = tid + 256 * j;           // 0..1023
                int r = s2 >> 3, kb = (s2 & 7) + 8 * h;
                uint32_t off = (uint32_t)(r * 256) + (uint32_t)((kb * 16) ^ ((r & 7) * 16));
                int sg = r * 16 + kb;
                CP_ASYNC16(smA + off, srcA + sg);
                CP_ASYNC16(smB + off, srcB + sg);
            }
            CP_COMMIT;
        }
    }

    // ---- fragment addresses ----
    int rA = wr * 64 + (lane & 7) + ((lane >> 3) & 1) * 8;
    uint32_t xorA = (uint32_t)((rA & 7) << 4);
    int kbA_half = (lane >> 4);
    uint32_t baseA[4];
    #pragma unroll
    for (int mi = 0; mi < 4; mi++) baseA[mi] = smA + (uint32_t)((rA + mi * 16) * 256);

    int rB = wc * 32 + (lane & 7);
    uint32_t xorB = (uint32_t)((rB & 7) << 4);
    int kbB_half = (lane >> 3) & 1;
    uint32_t baseB[4];
    #pragma unroll
    for (int ni = 0; ni < 4; ni++) baseB[ni] = smB + (uint32_t)((rB + ni * 8) * 256);

    float acc[4][4][4];
    #pragma unroll
    for (int mi = 0; mi < 4; mi++)
        #pragma unroll
        for (int ni = 0; ni < 4; ni++)
            #pragma unroll
            for (int e = 0; e < 4; e++) acc[mi][ni][e] = 0.0f;

    // ---- mainloop: two pipelined halves of 4 k-steps ----
    #pragma unroll
    for (int half = 0; half < 2; half++) {
        if (half == 0) { CP_WAIT(1); } else { CP_WAIT(0); }
        __syncthreads();
        #pragma unroll
        for (int kss = 0; kss < 4; kss++) {
            int ks = half * 4 + kss;
            uint32_t a[4][4], b[4][2];
            uint32_t kbA = (uint32_t)((ks * 2 + kbA_half) * 16);
            #pragma unroll
            for (int mi = 0; mi < 4; mi++)
                LDSM_X4(a[mi][0], a[mi][1], a[mi][2], a[mi][3], baseA[mi] + (kbA ^ xorA));
            uint32_t kbB = (uint32_t)((ks * 2 + kbB_half) * 16);
            #pragma unroll
            for (int ni = 0; ni < 4; ni++)
                LDSM_X2(b[ni][0], b[ni][1], baseB[ni] + (kbB ^ xorB));
            #pragma unroll
            for (int mi = 0; mi < 4; mi++)
                #pragma unroll
                for (int ni = 0; ni < 4; ni++)
                    MMA16816(acc[mi][ni], a[mi][0], a[mi][1], a[mi][2], a[mi][3],
                             b[ni][0], b[ni][1]);
        }
    }

    // ---- epilogue: exp2 + per-warp reduce, staged in smem ----
    int g = lane >> 2, th = lane & 3;
    float rsum[4][2], csum[4][2];
    #pragma unroll
    for (int i = 0; i < 4; i++) { rsum[i][0] = rsum[i][1] = 0.0f;
                                  csum[i][0] = csum[i][1] = 0.0f; }

#define EPI_BODY(DIAG, PB)                                                     \
    _Pragma("unroll")                                                          \
    for (int mi = 0; mi < 4; mi++) {                                           \
        int gi_b = row0 + wr * 64 + mi * 16 + g;                               \
        _Pragma("unroll")                                                      \
        for (int ni = 0; ni < 4; ni++) {                                       \
            int gj_b = col0 + wc * 32 + ni * 8 + th * 2;                       \
            _Pragma("unroll")                                                  \
            for (int e = 0; e < 4; e++) {                                      \
                int h = e >> 1, p = e & 1;                                     \
                float v = acc[mi][ni][e];                                      \
                if (PB && (gj_b + p) == (gi_b + h * 8) + NN)                   \
                    g_partner[gi_b + h * 8] = v;                               \
                float ex = exp2f(v - CB2);                                     \
                if (DIAG && (gj_b + p) <= (gi_b + h * 8)) ex = 0.0f;           \
                rsum[mi][h] += ex;                                             \
                csum[ni][p] += ex;                                             \
            }                                                                  \
        }                                                                      \
    }

    if (diag) { EPI_BODY(true, false) }
    else if (pblock) { EPI_BODY(false, true) }
    else { EPI_BODY(false, false) }
#undef EPI_BODY

    __syncthreads();            // all LDSM reads done; reuse smem as scratch
    float* rowscr = (float*)smem;            // [128][4]
    float* colscr = (float*)(smem + 2048);   // [128][2]

    #pragma unroll
    for (int mi = 0; mi < 4; mi++)
        #pragma unroll
        for (int h = 0; h < 2; h++) {
            float v = rsum[mi][h];
            v += __shfl_xor_sync(0xffffffffu, v, 1);
            v += __shfl_xor_sync(0xffffffffu, v, 2);
            if (th == 0)
                rowscr[(wr * 64 + mi * 16 + g + h * 8) * 4 + wc] = v;
        }

    #pragma unroll
    for (int ni = 0; ni < 4; ni++)
        #pragma unroll
        for (int p = 0; p < 2; p++) {
            float v = csum[ni][p];
            v += __shfl_xor_sync(0xffffffffu, v, 4);
            v += __shfl_xor_sync(0xffffffffu, v, 8);
            v += __shfl_xor_sync(0xffffffffu, v, 16);
            if (lane < 4)
                colscr[(wc * 32 + ni * 8 + lane * 2 + p) * 2 + wr] = v;
        }
    __syncthreads();

    if (tid < 128) {
        float s = rowscr[tid * 4] + rowscr[tid * 4 + 1]
                + rowscr[tid * 4 + 2] + rowscr[tid * 4 + 3];
        atomicAdd(&g_rowsum[row0 + tid], s);
    } else {
        int c = tid - 128;
        float s = colscr[c * 2] + colscr[c * 2 + 1];
        atomicAdd(&g_rowsum[col0 + c], s);
    }
}

// ---------------------------------------------------------------------------
// Kernel 3: finalize. u = log2e*sim/T domain.
// ---------------------------------------------------------------------------
__global__ void finalize_kernel(float* __restrict__ out) {
    int tid = threadIdx.x;
    float local = 0.0f;
    for (int i = tid; i < MM; i += 1024) {
        float u = g_partner[(i < NN) ? i : i - NN];
        float pos2 = 2.0f * u;                       // log2 domain
        float lse = logf(g_rowsum[i] + exp2f(pos2 - CB2)) + 10.0f;
        local += lse - pos2 * LN2;
    }
    #pragma unroll
    for (int o = 16; o; o >>= 1) local += __shfl_xor_sync(0xffffffffu, local, o);
    __shared__ float sr[32];
    if ((tid & 31) == 0) sr[tid >> 5] = local;
    __syncthreads();
    if (tid < 32) {
        float v = sr[tid];
        #pragma unroll
        for (int o = 16; o; o >>= 1) v += __shfl_xor_sync(0xffffffffu, v, o);
        if (tid == 0) out[0] = v / ((float)MM * (float)MM);
    }
}

extern "C" void kernel_launch(void* const* d_in, const int* in_sizes, int n_in,
                              void* d_out, int out_size) {
    const float* z1 = (const float*)d_in[0];
    const float* z2 = (const float*)d_in[1];
    float* out = (float*)d_out;

    cudaFuncSetAttribute(sim_kernel, cudaFuncAttributeMaxDynamicSharedMemorySize, 65536);

    normalize_kernel<<<NN / 32, 1024>>>(z1, z2);
    sim_kernel<<<NTRI, 256, 65536>>>();
    finalize_kernel<<<1, 1024>>>(out);
}

// round 9
// speedup vs baseline: 10.0706x; 1.0528x over previous
#include <cuda_runtime.h>
#include <cuda_bf16.h>
#include <math.h>
#include <cstdint>

#define NN 4096
#define MM 8192
#define DD 128
#define NTILE 64
#define NCTAS 1056   // sum over rt of (32 - rt/2)

// operands pre-scaled by sqrt(10 * log2(e)) so acc = log2(e) * sim / T
#define SCALE_IN 3.798282100420615f
#define CB2 14.426950408889634f          // 10 * log2(e)
#define LN2 0.6931471805599453f

// ---------------- device globals (no allocs allowed) ----------------------
__device__ __align__(16) __nv_bfloat16 g_zbf[MM * DD];
__device__ float g_rowsum[MM];
__device__ float g_partner[NN];   // log2e * sim[i, i+N] / T
__device__ unsigned int g_done;

// ---------------- helpers --------------------------------------------------
__device__ __forceinline__ uint32_t smem_to_u32(const void* p) {
    uint32_t a;
    asm("{ .reg .u64 t; cvta.to.shared.u64 t, %1; cvt.u32.u64 %0, t; }"
        : "=r"(a) : "l"(p));
    return a;
}

#define LDSM_X4(r0, r1, r2, r3, addr)                                          \
    asm volatile("ldmatrix.sync.aligned.m8n8.x4.shared.b16 {%0,%1,%2,%3}, [%4];" \
        : "=r"(r0), "=r"(r1), "=r"(r2), "=r"(r3) : "r"(addr))

#define MMA16816(d, a0, a1, a2, a3, b0, b1)                                    \
    asm volatile("mma.sync.aligned.m16n8k16.row.col.f32.bf16.bf16.f32 "        \
        "{%0,%1,%2,%3}, {%4,%5,%6,%7}, {%8,%9}, {%0,%1,%2,%3};"                \
        : "+f"((d)[0]), "+f"((d)[1]), "+f"((d)[2]), "+f"((d)[3])               \
        : "r"(a0), "r"(a1), "r"(a2), "r"(a3), "r"(b0), "r"(b1))

#define CP_ASYNC16(sm, gp)                                                     \
    asm volatile("cp.async.cg.shared.global [%0], [%1], 16;"                   \
        :: "r"(sm), "l"(gp) : "memory")
#define CP_COMMIT  asm volatile("cp.async.commit_group;" ::: "memory")
#define CP_WAIT(n) asm volatile("cp.async.wait_group %0;" :: "n"(n) : "memory")

// ---------------------------------------------------------------------------
// Kernel 1: warp handles paired rows r (z1) and r+NN (z2); 512-thread blocks
// for full-chip spread. Zeroes g_rowsum and g_done.
// ---------------------------------------------------------------------------
__global__ void __launch_bounds__(512) normalize_kernel(
        const float* __restrict__ z1, const float* __restrict__ z2) {
    int r = (blockIdx.x * 512 + threadIdx.x) >> 5;   // 0..NN-1
    int lane = threadIdx.x & 31;
    if (blockIdx.x == 0 && threadIdx.x == 0) g_done = 0;
    float4 a = ((const float4*)(z1 + (size_t)r * DD))[lane];
    float4 b = ((const float4*)(z2 + (size_t)r * DD))[lane];
    float sa = a.x * a.x + a.y * a.y + a.z * a.z + a.w * a.w;
    float sb = b.x * b.x + b.y * b.y + b.z * b.z + b.w * b.w;
    #pragma unroll
    for (int o = 16; o; o >>= 1) {
        sa += __shfl_xor_sync(0xffffffffu, sa, o);
        sb += __shfl_xor_sync(0xffffffffu, sb, o);
    }
    float ia = SCALE_IN * rsqrtf(sa);
    float ib = SCALE_IN * rsqrtf(sb);
    __nv_bfloat162 a0 = {__float2bfloat16(a.x * ia), __float2bfloat16(a.y * ia)};
    __nv_bfloat162 a1 = {__float2bfloat16(a.z * ia), __float2bfloat16(a.w * ia)};
    __nv_bfloat162 b0 = {__float2bfloat16(b.x * ib), __float2bfloat16(b.y * ib)};
    __nv_bfloat162 b1 = {__float2bfloat16(b.z * ib), __float2bfloat16(b.w * ib)};
    uint2 oa, ob;
    oa.x = *(uint32_t*)&a0; oa.y = *(uint32_t*)&a1;
    ob.x = *(uint32_t*)&b0; ob.y = *(uint32_t*)&b1;
    ((uint2*)(g_zbf + (size_t)r * DD))[lane] = oa;
    ((uint2*)(g_zbf + (size_t)(r + NN) * DD))[lane] = ob;
    if (lane == 0) { g_rowsum[r] = 0.0f; g_rowsum[r + NN] = 0.0f; }
}

// ---------------------------------------------------------------------------
// 4 k-steps of m16n8k16 over one 64-k half.
// ---------------------------------------------------------------------------
__device__ __forceinline__ void compute_half(
        const uint32_t* baseA, const uint32_t* baseBp,
        uint32_t xorA, uint32_t xorB, int kbA_half, int kbB_half,
        int half, float (*acc)[4][4]) {
    #pragma unroll
    for (int kss = 0; kss < 4; kss++) {
        int ks = half * 4 + kss;
        uint32_t a[4][4], b[4][2];
        uint32_t kbA = (uint32_t)((ks * 2 + kbA_half) * 16);
        #pragma unroll
        for (int mi = 0; mi < 4; mi++)
            LDSM_X4(a[mi][0], a[mi][1], a[mi][2], a[mi][3], baseA[mi] + (kbA ^ xorA));
        uint32_t kbB = (uint32_t)((ks * 2 + kbB_half) * 16);
        #pragma unroll
        for (int pi = 0; pi < 2; pi++)
            LDSM_X4(b[2 * pi][0], b[2 * pi][1], b[2 * pi + 1][0], b[2 * pi + 1][1],
                    baseBp[pi] + (kbB ^ xorB));
        #pragma unroll
        for (int mi = 0; mi < 4; mi++)
            #pragma unroll
            for (int ni = 0; ni < 4; ni++)
                MMA16816(acc[mi][ni], a[mi][0], a[mi][1], a[mi][2], a[mi][3],
                         b[ni][0], b[ni][1]);
    }
}

// ---------------------------------------------------------------------------
// Kernel 2: each CTA computes a 128x256 slab = two 128x128 sim tiles sharing
// one A tile. Upper-triangular coverage; fused exp2 epilogue; last CTA
// finalizes the loss.
// smem: A 32K | B0 32K | B1 32K | colscr0 1K | colscr1 1K | rowscr 2K
// ---------------------------------------------------------------------------
__global__ void __launch_bounds__(256, 2) sim_kernel(float* __restrict__ out) {
    // unrank blockIdx.x -> (rt, ctp): ctp_min = rt>>1, count = 32 - (rt>>1)
    int rt = 0, rem = blockIdx.x;
    #pragma unroll 1
    while (rem >= 32 - (rt >> 1)) { rem -= 32 - (rt >> 1); rt++; }
    int ctp = (rt >> 1) + rem;
    int ct0 = 2 * ctp, ct1 = ct0 + 1;
    // modes: 0=skip, 1=diag, 2=pblock, 3=plain
    int m0 = (ct0 < rt) ? 0 : (ct0 == rt) ? 1 : (ct0 == rt + 32) ? 2 : 3;
    int m1 = (ct1 == rt) ? 1 : (ct1 == rt + 32) ? 2 : 3;

    extern __shared__ __align__(128) unsigned char smem[];
    uint32_t sb = smem_to_u32(smem);
    uint32_t smA = sb, smB0 = sb + 32768, smB1 = sb + 65536;
    float* colscr0 = (float*)(smem + 98304);
    float* colscr1 = (float*)(smem + 99328);
    float* rowscr  = (float*)(smem + 100352);

    int tid = threadIdx.x;
    int lane = tid & 31, wid = tid >> 5;
    int wr = wid >> 2, wc = wid & 3;        // 2x4 warps; warp tile 64r x 32c
    int row0 = rt * 128;
    int col0_0 = ct0 * 128, col0_1 = ct1 * 128;

    // ---- async loads: groups g0={A.h0,B0.h0} g1={A.h1,B0.h1} g2={B1.h0} g3={B1.h1}
    {
        const uint4* srcA  = (const uint4*)(g_zbf + (size_t)row0 * DD);
        const uint4* srcB0 = (const uint4*)(g_zbf + (size_t)col0_0 * DD);
        const uint4* srcB1 = (const uint4*)(g_zbf + (size_t)col0_1 * DD);
        #pragma unroll
        for (int h = 0; h < 2; h++) {
            #pragma unroll
            for (int j = 0; j < 4; j++) {
                int s2 = tid + 256 * j;
                int r = s2 >> 3, kb = (s2 & 7) + 8 * h;
                uint32_t off = (uint32_t)(r * 256) + (uint32_t)((kb * 16) ^ ((r & 7) * 16));
                int sg = r * 16 + kb;
                CP_ASYNC16(smA + off, srcA + sg);
                CP_ASYNC16(smB0 + off, srcB0 + sg);
            }
            CP_COMMIT;
        }
        #pragma unroll
        for (int h = 0; h < 2; h++) {
            #pragma unroll
            for (int j = 0; j < 4; j++) {
                int s2 = tid + 256 * j;
                int r = s2 >> 3, kb = (s2 & 7) + 8 * h;
                uint32_t off = (uint32_t)(r * 256) + (uint32_t)((kb * 16) ^ ((r & 7) * 16));
                int sg = r * 16 + kb;
                CP_ASYNC16(smB1 + off, srcB1 + sg);
            }
            CP_COMMIT;
        }
    }

    // ---- fragment addresses ----
    int rA = wr * 64 + (lane & 7) + ((lane >> 3) & 1) * 8;
    uint32_t xorA = (uint32_t)((rA & 7) << 4);
    int kbA_half = (lane >> 4);
    uint32_t baseA[4];
    #pragma unroll
    for (int mi = 0; mi < 4; mi++) baseA[mi] = smA + (uint32_t)((rA + mi * 16) * 256);

    // B via x4 over ni-pairs: lanes 0-7:(2pi,kh0) 8-15:(2pi,kh1) 16-23:(2pi+1,kh0) 24-31:(2pi+1,kh1)
    int rB = wc * 32 + ((lane >> 4) & 1) * 8 + (lane & 7);   // + pi*16
    uint32_t xorB = (uint32_t)((lane & 7) << 4);
    int kbB_half = (lane >> 3) & 1;
    uint32_t baseB0[2], baseB1[2];
    #pragma unroll
    for (int pi = 0; pi < 2; pi++) {
        baseB0[pi] = smB0 + (uint32_t)((rB + pi * 16) * 256);
        baseB1[pi] = smB1 + (uint32_t)((rB + pi * 16) * 256);
    }

    int g = lane >> 2, th = lane & 3;
    float rsum[4][2];
    #pragma unroll
    for (int i = 0; i < 4; i++) { rsum[i][0] = 0.0f; rsum[i][1] = 0.0f; }

    float acc[4][4][4];

// epilogue for one tile: exp2, rsum accumulation, csum -> colscr
#define EPILOGUE(COL0, MODE, COLSCR) do {                                      \
    float csum[4][2];                                                          \
    _Pragma("unroll")                                                          \
    for (int i = 0; i < 4; i++) { csum[i][0] = 0.0f; csum[i][1] = 0.0f; }      \
    _Pragma("unroll")                                                          \
    for (int mi = 0; mi < 4; mi++) {                                           \
        int gi_b = row0 + wr * 64 + mi * 16 + g;                               \
        _Pragma("unroll")                                                      \
        for (int ni = 0; ni < 4; ni++) {                                       \
            int gj_b = (COL0) + wc * 32 + ni * 8 + th * 2;                     \
            _Pragma("unroll")                                                  \
            for (int e = 0; e < 4; e++) {                                      \
                int h = e >> 1, p = e & 1;                                     \
                float v = acc[mi][ni][e];                                      \
                if ((MODE) == 2 && (gj_b + p) == (gi_b + h * 8) + NN)          \
                    g_partner[gi_b + h * 8] = v;                               \
                float ex = exp2f(v - CB2);                                     \
                if ((MODE) == 1 && (gj_b + p) <= (gi_b + h * 8)) ex = 0.0f;    \
                rsum[mi][h] += ex;                                             \
                csum[ni][p] += ex;                                             \
            }                                                                  \
        }                                                                      \
    }                                                                          \
    _Pragma("unroll")                                                          \
    for (int ni = 0; ni < 4; ni++)                                             \
        _Pragma("unroll")                                                      \
        for (int p = 0; p < 2; p++) {                                          \
            float v = csum[ni][p];                                             \
            v += __shfl_xor_sync(0xffffffffu, v, 4);                           \
            v += __shfl_xor_sync(0xffffffffu, v, 8);                           \
            v += __shfl_xor_sync(0xffffffffu, v, 16);                          \
            if (lane < 4)                                                      \
                (COLSCR)[(wc * 32 + ni * 8 + lane * 2 + p) * 2 + wr] = v;      \
        }                                                                      \
} while (0)

    // ---- tile 0 ----
    CP_WAIT(3);
    __syncthreads();
    if (m0 != 0) {
        #pragma unroll
        for (int mi = 0; mi < 4; mi++)
            #pragma unroll
            for (int ni = 0; ni < 4; ni++)
                #pragma unroll
                for (int e = 0; e < 4; e++) acc[mi][ni][e] = 0.0f;
        compute_half(baseA, baseB0, xorA, xorB, kbA_half, kbB_half, 0, acc);
        CP_WAIT(2);
        __syncthreads();
        compute_half(baseA, baseB0, xorA, xorB, kbA_half, kbB_half, 1, acc);
        if (m0 == 1) { EPILOGUE(col0_0, 1, colscr0); }
        else if (m0 == 2) { EPILOGUE(col0_0, 2, colscr0); }
        else { EPILOGUE(col0_0, 3, colscr0); }
    } else {
        CP_WAIT(2);
        __syncthreads();
    }

    // ---- tile 1 ----
    CP_WAIT(1);
    __syncthreads();
    #pragma unroll
    for (int mi = 0; mi < 4; mi++)
        #pragma unroll
        for (int ni = 0; ni < 4; ni++)
            #pragma unroll
            for (int e = 0; e < 4; e++) acc[mi][ni][e] = 0.0f;
    compute_half(baseA, baseB1, xorA, xorB, kbA_half, kbB_half, 0, acc);
    CP_WAIT(0);
    __syncthreads();
    compute_half(baseA, baseB1, xorA, xorB, kbA_half, kbB_half, 1, acc);
    if (m1 == 1) { EPILOGUE(col0_1, 1, colscr1); }
    else if (m1 == 2) { EPILOGUE(col0_1, 2, colscr1); }
    else { EPILOGUE(col0_1, 3, colscr1); }
#undef EPILOGUE

    // ---- row sums (accumulated over both tiles) -> rowscr ----
    #pragma unroll
    for (int mi = 0; mi < 4; mi++)
        #pragma unroll
        for (int h = 0; h < 2; h++) {
            float v = rsum[mi][h];
            v += __shfl_xor_sync(0xffffffffu, v, 1);
            v += __shfl_xor_sync(0xffffffffu, v, 2);
            if (th == 0)
                rowscr[(wr * 64 + mi * 16 + g + h * 8) * 4 + wc] = v;
        }
    __syncthreads();

    if (tid < 128) {
        float s = rowscr[tid * 4] + rowscr[tid * 4 + 1]
                + rowscr[tid * 4 + 2] + rowscr[tid * 4 + 3];
        atomicAdd(&g_rowsum[row0 + tid], s);
    } else {
        int c = tid - 128;
        if (m0 != 0) {
            float s0 = colscr0[c * 2] + colscr0[c * 2 + 1];
            atomicAdd(&g_rowsum[col0_0 + c], s0);
        }
        float s1 = colscr1[c * 2] + colscr1[c * 2 + 1];
        atomicAdd(&g_rowsum[col0_1 + c], s1);
    }

    // ---- last CTA finalizes ----
    __threadfence();
    __syncthreads();
    __shared__ unsigned int s_last;
    if (tid == 0) s_last = (atomicAdd(&g_done, 1u) == NCTAS - 1) ? 1u : 0u;
    __syncthreads();
    if (s_last) {
        float local = 0.0f;
        #pragma unroll 4
        for (int j = 0; j < 32; j++) {
            int i = tid + j * 256;
            float u = g_partner[(i < NN) ? i : i - NN];
            float pos2 = 2.0f * u;                       // log2 domain
            float lse = logf(g_rowsum[i] + exp2f(pos2 - CB2)) + 10.0f;
            local += lse - pos2 * LN2;
        }
        #pragma unroll
        for (int o = 16; o; o >>= 1) local += __shfl_xor_sync(0xffffffffu, local, o);
        if (lane == 0) rowscr[wid] = local;
        __syncthreads();
        if (tid == 0) {
            float v = 0.0f;
            #pragma unroll
            for (int w = 0; w < 8; w++) v += rowscr[w];
            out[0] = v / ((float)MM * (float)MM);
        }
    }
}

extern "C" void kernel_launch(void* const* d_in, const int* in_sizes, int n_in,
                              void* d_out, int out_size) {
    const float* z1 = (const float*)d_in[0];
    const float* z2 = (const float*)d_in[1];
    float* out = (float*)d_out;

    cudaFuncSetAttribute(sim_kernel, cudaFuncAttributeMaxDynamicSharedMemorySize, 102400);

    normalize_kernel<<<NN / 16, 512>>>(z1, z2);
    sim_kernel<<<NCTAS, 256, 102400>>>(out);
}